// round 2
// baseline (speedup 1.0000x reference)
#include <cuda_runtime.h>
#include <math.h>

#define N_NODES 100000
#define N_EDGES 800000
#define VOCAB   256
#define DIM     256
#define N_MASK  10000
#define R2      16      // masked rows per block in layer-2 fused kernel

// ---------------- scratch (device globals; no runtime allocation) ----------
__device__ int   g_deg[N_NODES];
__device__ float g_dinv[N_NODES];
__device__ int   g_rowstart[N_NODES + 1];
__device__ int   g_cursor[N_NODES];
__device__ int   g_csr_src[N_EDGES];
__device__ float g_EW1[VOCAB * DIM];
__device__ float g_h1[(size_t)N_NODES * DIM];

// ---------------- helpers ----------------
__device__ __forceinline__ float4 fma4(float w, float4 a, float4 acc) {
    acc.x = fmaf(w, a.x, acc.x);
    acc.y = fmaf(w, a.y, acc.y);
    acc.z = fmaf(w, a.z, acc.z);
    acc.w = fmaf(w, a.w, acc.w);
    return acc;
}

// ---------------- CSR construction ----------------
__global__ void k_init_deg() {
    int i = blockIdx.x * blockDim.x + threadIdx.x;
    if (i < N_NODES) g_deg[i] = 1;  // self loop
}

__global__ void k_hist(const int* __restrict__ dst) {
    int i = blockIdx.x * blockDim.x + threadIdx.x;
    if (i < N_EDGES) atomicAdd(&g_deg[dst[i]], 1);
}

__global__ void k_dinv() {
    int i = blockIdx.x * blockDim.x + threadIdx.x;
    if (i < N_NODES) g_dinv[i] = rsqrtf((float)g_deg[i]);
}

// single-block exclusive scan of (deg-1) -> rowstart, also seeds cursor
__global__ void k_scan() {
    __shared__ int ssum[1024];
    const int t   = threadIdx.x;
    const int SEG = (N_NODES + 1023) / 1024;  // 98
    int lo = t * SEG;
    int hi = lo + SEG; if (hi > N_NODES) hi = N_NODES;
    if (lo > N_NODES) lo = N_NODES;

    int s = 0;
    for (int i = lo; i < hi; i++) s += g_deg[i] - 1;
    ssum[t] = s;
    __syncthreads();
    // Hillis-Steele inclusive scan
    for (int off = 1; off < 1024; off <<= 1) {
        int v = (t >= off) ? ssum[t - off] : 0;
        __syncthreads();
        ssum[t] += v;
        __syncthreads();
    }
    int run = (t == 0) ? 0 : ssum[t - 1];
    for (int i = lo; i < hi; i++) {
        g_rowstart[i] = run;
        g_cursor[i]   = run;
        run += g_deg[i] - 1;
    }
    if (t == 1023) g_rowstart[N_NODES] = ssum[1023];
}

__global__ void k_fill(const int* __restrict__ src, const int* __restrict__ dst) {
    int i = blockIdx.x * blockDim.x + threadIdx.x;
    if (i < N_EDGES) {
        int d = dst[i];
        int p = atomicAdd(&g_cursor[d], 1);
        g_csr_src[p] = src[i];
    }
}

// ---------------- EW1 = emb @ W1 (256x256x256, trivial) ----------------
__global__ void k_ew1(const float* __restrict__ emb, const float* __restrict__ W1) {
    __shared__ float se[DIM];
    const int v = blockIdx.x;
    const int c = threadIdx.x;
    se[c] = emb[v * DIM + c];
    __syncthreads();
    float acc = 0.f;
#pragma unroll 8
    for (int k = 0; k < DIM; k++) acc = fmaf(se[k], W1[k * DIM + c], acc);
    g_EW1[v * DIM + c] = acc;
}

// ---------------- layer 1: h1 = relu(aggregate(EW1[x]) + b1), warp/node ----
__global__ void k_layer1(const int* __restrict__ x, const float* __restrict__ b1) {
    const int warp = blockIdx.x * (blockDim.x >> 5) + (threadIdx.x >> 5);
    if (warp >= N_NODES) return;
    const int lane = threadIdx.x & 31;
    const int n    = warp;

    const float4* EW = reinterpret_cast<const float4*>(g_EW1);
    const float dn = g_dinv[n];

    // self loop contribution
    int   v = x[n];
    float w = dn * dn;
    float4 q0 = EW[v * 64 + lane];
    float4 q1 = EW[v * 64 + 32 + lane];
    float4 a0 = make_float4(w * q0.x, w * q0.y, w * q0.z, w * q0.w);
    float4 a1 = make_float4(w * q1.x, w * q1.y, w * q1.z, w * q1.w);

    const int e0 = g_rowstart[n];
    const int e1 = g_rowstart[n + 1];
    for (int e = e0; e < e1; e++) {
        int s    = g_csr_src[e];        // lane-uniform: broadcast
        float ws = g_dinv[s] * dn;
        int  b   = x[s] * 64;
        float4 p0 = EW[b + lane];
        float4 p1 = EW[b + 32 + lane];
        a0 = fma4(ws, p0, a0);
        a1 = fma4(ws, p1, a1);
    }

    const float4* B = reinterpret_cast<const float4*>(b1);
    float4 bb0 = B[lane], bb1 = B[32 + lane];
    a0.x = fmaxf(a0.x + bb0.x, 0.f); a0.y = fmaxf(a0.y + bb0.y, 0.f);
    a0.z = fmaxf(a0.z + bb0.z, 0.f); a0.w = fmaxf(a0.w + bb0.w, 0.f);
    a1.x = fmaxf(a1.x + bb1.x, 0.f); a1.y = fmaxf(a1.y + bb1.y, 0.f);
    a1.z = fmaxf(a1.z + bb1.z, 0.f); a1.w = fmaxf(a1.w + bb1.w, 0.f);

    float4* H = reinterpret_cast<float4*>(g_h1);
    H[(size_t)n * 64 + lane]      = a0;
    H[(size_t)n * 64 + 32 + lane] = a1;
}

// ---------------- layer 2: agg -> GEMM(R2x256x256) -> log_softmax ----------
__global__ void __launch_bounds__(256) k_layer2(const int* __restrict__ mask,
                                                const float* __restrict__ W2,
                                                const float* __restrict__ b2,
                                                float* __restrict__ out) {
    __shared__ float sagg[DIM * R2];  // stage A: [k][i]; stage C: [i][k] outputs
    const int t  = threadIdx.x;
    const int r0 = blockIdx.x * R2;   // N_MASK / R2 = 625 exact

    // ---- stage A: aggregate h1 into R2 masked rows; thread t owns dim t ----
    for (int i = 0; i < R2; i++) {
        const int m  = mask[r0 + i];
        const float dm = g_dinv[m];
        float acc = dm * dm * g_h1[(size_t)m * DIM + t];
        const int e0 = g_rowstart[m];
        const int e1 = g_rowstart[m + 1];
        for (int e = e0; e < e1; e++) {
            int s = g_csr_src[e];
            acc = fmaf(g_dinv[s] * dm, g_h1[(size_t)s * DIM + t], acc);
        }
        sagg[t * R2 + i] = acc;  // transposed: [k=t][i]
    }
    __syncthreads();

    // ---- stage B: o[i][t] = b2[t] + sum_k agg[i][k] * W2[k][t] ----
    float o[R2];
    {
        const float bb = b2[t];
#pragma unroll
        for (int i = 0; i < R2; i++) o[i] = bb;
    }
#pragma unroll 4
    for (int k = 0; k < DIM; k++) {
        const float w = W2[k * DIM + t];
        const float4* A4 = reinterpret_cast<const float4*>(sagg + k * R2);
        float4 g0 = A4[0], g1 = A4[1], g2 = A4[2], g3 = A4[3];  // broadcast LDS
        o[0]  = fmaf(g0.x, w, o[0]);  o[1]  = fmaf(g0.y, w, o[1]);
        o[2]  = fmaf(g0.z, w, o[2]);  o[3]  = fmaf(g0.w, w, o[3]);
        o[4]  = fmaf(g1.x, w, o[4]);  o[5]  = fmaf(g1.y, w, o[5]);
        o[6]  = fmaf(g1.z, w, o[6]);  o[7]  = fmaf(g1.w, w, o[7]);
        o[8]  = fmaf(g2.x, w, o[8]);  o[9]  = fmaf(g2.y, w, o[9]);
        o[10] = fmaf(g2.z, w, o[10]); o[11] = fmaf(g2.w, w, o[11]);
        o[12] = fmaf(g3.x, w, o[12]); o[13] = fmaf(g3.y, w, o[13]);
        o[14] = fmaf(g3.z, w, o[14]); o[15] = fmaf(g3.w, w, o[15]);
    }
    __syncthreads();  // done reading sagg
#pragma unroll
    for (int i = 0; i < R2; i++) sagg[i * DIM + t] = o[i];  // now [i][k]
    __syncthreads();

    // ---- stage C: per-row log_softmax; warp wi handles rows wi, wi+8 ----
    const int wi   = t >> 5;
    const int lane = t & 31;
#pragma unroll
    for (int rr = 0; rr < 2; rr++) {
        const int i = wi + rr * 8;
        float v[8];
        float mx = -INFINITY;
#pragma unroll
        for (int j = 0; j < 8; j++) {
            v[j] = sagg[i * DIM + lane + j * 32];
            mx = fmaxf(mx, v[j]);
        }
#pragma unroll
        for (int off = 16; off > 0; off >>= 1)
            mx = fmaxf(mx, __shfl_xor_sync(0xFFFFFFFFu, mx, off));
        float s = 0.f;
#pragma unroll
        for (int j = 0; j < 8; j++) s += expf(v[j] - mx);
#pragma unroll
        for (int off = 16; off > 0; off >>= 1)
            s += __shfl_xor_sync(0xFFFFFFFFu, s, off);
        const float lse = mx + logf(s);
        float* orow = out + (size_t)(r0 + i) * DIM;
#pragma unroll
        for (int j = 0; j < 8; j++) orow[lane + j * 32] = v[j] - lse;
    }
}

// ---------------- launch ----------------
extern "C" void kernel_launch(void* const* d_in, const int* in_sizes, int n_in,
                              void* d_out, int out_size) {
    const int*   x    = (const int*)d_in[0];           // (100000,1) int32
    const int*   esrc = (const int*)d_in[1];           // edge_index[0]
    const int*   edst = ((const int*)d_in[1]) + N_EDGES; // edge_index[1]
    const int*   mask = (const int*)d_in[2];           // (10000,) int32
    const float* emb  = (const float*)d_in[3];         // (256,256)
    const float* W1   = (const float*)d_in[4];         // (256,256)
    const float* b1   = (const float*)d_in[5];         // (256,)
    const float* W2   = (const float*)d_in[6];         // (256,256)
    const float* b2   = (const float*)d_in[7];         // (256,)
    float*       out  = (float*)d_out;                 // (10000,256)

    const int TB = 256;
    k_init_deg<<<(N_NODES + TB - 1) / TB, TB>>>();
    k_hist<<<(N_EDGES + TB - 1) / TB, TB>>>(edst);
    k_dinv<<<(N_NODES + TB - 1) / TB, TB>>>();
    k_scan<<<1, 1024>>>();
    k_fill<<<(N_EDGES + TB - 1) / TB, TB>>>(esrc, edst);
    k_ew1<<<VOCAB, DIM>>>(emb, W1);
    k_layer1<<<(N_NODES + 7) / 8, 256>>>(x, b1);   // warp per node
    k_layer2<<<N_MASK / R2, 256>>>(mask, W2, b2, out);
}

// round 3
// speedup vs baseline: 1.8245x; 1.8245x over previous
#include <cuda_runtime.h>
#include <math.h>

#define N_NODES 100000
#define N_EDGES 800000
#define VOCAB   256
#define DIM     256
#define N_MASK  10000
#define R2      16
#define SCAN_B  1024
#define NBLK    ((N_NODES + SCAN_B - 1) / SCAN_B)   // 98

// ---------------- scratch (device globals; no runtime allocation) ----------
__device__ int   g_deg[N_NODES];
__device__ float g_dinv[N_NODES];
__device__ int   g_rowstart[N_NODES + 1];
__device__ int   g_cursor[N_NODES];
__device__ int   g_csr_src[N_EDGES];
__device__ int   g_blocksum[NBLK];
__device__ int   g_blockoff[NBLK];
__device__ float g_EW1[VOCAB * DIM];
__device__ float g_h1[(size_t)N_NODES * DIM];

// ---------------- helpers ----------------
__device__ __forceinline__ float4 fma4(float w, float4 a, float4 acc) {
    acc.x = fmaf(w, a.x, acc.x);
    acc.y = fmaf(w, a.y, acc.y);
    acc.z = fmaf(w, a.z, acc.z);
    acc.w = fmaf(w, a.w, acc.w);
    return acc;
}

__device__ __forceinline__ int warp_incl_scan(int v, int lane) {
#pragma unroll
    for (int off = 1; off < 32; off <<= 1) {
        int n = __shfl_up_sync(0xFFFFFFFFu, v, off);
        if (lane >= off) v += n;
    }
    return v;
}

// ---------------- CSR construction ----------------
__global__ void k_init_deg() {
    int i = blockIdx.x * blockDim.x + threadIdx.x;
    if (i < N_NODES) g_deg[i] = 1;  // self loop
}

__global__ void k_hist(const int* __restrict__ dst) {
    int i = blockIdx.x * blockDim.x + threadIdx.x;
    if (i < N_EDGES) atomicAdd(&g_deg[dst[i]], 1);
}

// stage 1: per-block sums of (deg-1)
__global__ void __launch_bounds__(SCAN_B) k_blocksum() {
    __shared__ int wsum[32];
    const int t    = threadIdx.x;
    const int lane = t & 31;
    const int wid  = t >> 5;
    const int i    = blockIdx.x * SCAN_B + t;
    int v = (i < N_NODES) ? g_deg[i] - 1 : 0;
#pragma unroll
    for (int off = 16; off > 0; off >>= 1) v += __shfl_xor_sync(0xFFFFFFFFu, v, off);
    if (lane == 0) wsum[wid] = v;
    __syncthreads();
    if (wid == 0) {
        int s = wsum[lane];
#pragma unroll
        for (int off = 16; off > 0; off >>= 1) s += __shfl_xor_sync(0xFFFFFFFFu, s, off);
        if (lane == 0) g_blocksum[blockIdx.x] = s;
    }
}

// stage 2: exclusive scan of the 98 block sums (one tiny block)
__global__ void k_scanblocks() {
    __shared__ int ws[4];
    const int t    = threadIdx.x;     // 128 threads
    const int lane = t & 31;
    const int wid  = t >> 5;
    int v = (t < NBLK) ? g_blocksum[t] : 0;
    int incl = warp_incl_scan(v, lane);
    if (lane == 31) ws[wid] = incl;
    __syncthreads();
    if (t == 0) {
        int run = 0;
#pragma unroll
        for (int w = 0; w < 4; w++) { int tmp = ws[w]; ws[w] = run; run += tmp; }
    }
    __syncthreads();
    if (t < NBLK) g_blockoff[t] = incl - v + ws[wid];
}

// stage 3: per-block exclusive scan + block offset -> rowstart/cursor; fold dinv
__global__ void __launch_bounds__(SCAN_B) k_scanfinal() {
    __shared__ int wsum[32];
    const int t    = threadIdx.x;
    const int lane = t & 31;
    const int wid  = t >> 5;
    const int i    = blockIdx.x * SCAN_B + t;
    const int deg  = (i < N_NODES) ? g_deg[i] : 1;
    const int v    = deg - 1;
    int incl = warp_incl_scan(v, lane);
    if (lane == 31) wsum[wid] = incl;
    __syncthreads();
    if (wid == 0) wsum[lane] = warp_incl_scan(wsum[lane], lane);
    __syncthreads();
    int excl = incl - v + (wid ? wsum[wid - 1] : 0) + g_blockoff[blockIdx.x];
    if (i < N_NODES) {
        g_rowstart[i] = excl;
        g_cursor[i]   = excl;
        g_dinv[i]     = rsqrtf((float)deg);
        if (i == N_NODES - 1) g_rowstart[N_NODES] = excl + v;
    }
}

__global__ void k_fill(const int* __restrict__ src, const int* __restrict__ dst) {
    int i = blockIdx.x * blockDim.x + threadIdx.x;
    if (i < N_EDGES) {
        int d = dst[i];
        int p = atomicAdd(&g_cursor[d], 1);
        g_csr_src[p] = src[i];
    }
}

// ---------------- EW1 = emb @ W1 (256x256x256, trivial) ----------------
__global__ void k_ew1(const float* __restrict__ emb, const float* __restrict__ W1) {
    __shared__ float se[DIM];
    const int v = blockIdx.x;
    const int c = threadIdx.x;
    se[c] = emb[v * DIM + c];
    __syncthreads();
    float acc = 0.f;
#pragma unroll 8
    for (int k = 0; k < DIM; k++) acc = fmaf(se[k], W1[k * DIM + c], acc);
    g_EW1[v * DIM + c] = acc;
}

// ---------------- layer 1: h1 = relu(aggregate(EW1[x]) + b1), warp/node ----
__global__ void k_layer1(const int* __restrict__ x, const float* __restrict__ b1) {
    const int warp = blockIdx.x * (blockDim.x >> 5) + (threadIdx.x >> 5);
    if (warp >= N_NODES) return;
    const int lane = threadIdx.x & 31;
    const int n    = warp;

    const float4* EW = reinterpret_cast<const float4*>(g_EW1);
    const float dn = g_dinv[n];

    int   v = x[n];
    float w = dn * dn;
    float4 q0 = EW[v * 64 + lane];
    float4 q1 = EW[v * 64 + 32 + lane];
    float4 a0 = make_float4(w * q0.x, w * q0.y, w * q0.z, w * q0.w);
    float4 a1 = make_float4(w * q1.x, w * q1.y, w * q1.z, w * q1.w);

    const int e0 = g_rowstart[n];
    const int e1 = g_rowstart[n + 1];
    for (int e = e0; e < e1; e++) {
        int s    = g_csr_src[e];
        float ws = g_dinv[s] * dn;
        int  b   = x[s] * 64;
        float4 p0 = EW[b + lane];
        float4 p1 = EW[b + 32 + lane];
        a0 = fma4(ws, p0, a0);
        a1 = fma4(ws, p1, a1);
    }

    const float4* B = reinterpret_cast<const float4*>(b1);
    float4 bb0 = B[lane], bb1 = B[32 + lane];
    a0.x = fmaxf(a0.x + bb0.x, 0.f); a0.y = fmaxf(a0.y + bb0.y, 0.f);
    a0.z = fmaxf(a0.z + bb0.z, 0.f); a0.w = fmaxf(a0.w + bb0.w, 0.f);
    a1.x = fmaxf(a1.x + bb1.x, 0.f); a1.y = fmaxf(a1.y + bb1.y, 0.f);
    a1.z = fmaxf(a1.z + bb1.z, 0.f); a1.w = fmaxf(a1.w + bb1.w, 0.f);

    float4* H = reinterpret_cast<float4*>(g_h1);
    H[(size_t)n * 64 + lane]      = a0;
    H[(size_t)n * 64 + 32 + lane] = a1;
}

// ---------------- layer 2: agg -> GEMM(R2x256x256) -> log_softmax ----------
__global__ void __launch_bounds__(256) k_layer2(const int* __restrict__ mask,
                                                const float* __restrict__ W2,
                                                const float* __restrict__ b2,
                                                float* __restrict__ out) {
    __shared__ float sagg[DIM * R2];
    const int t  = threadIdx.x;
    const int r0 = blockIdx.x * R2;

    for (int i = 0; i < R2; i++) {
        const int m  = mask[r0 + i];
        const float dm = g_dinv[m];
        float acc = dm * dm * g_h1[(size_t)m * DIM + t];
        const int e0 = g_rowstart[m];
        const int e1 = g_rowstart[m + 1];
        for (int e = e0; e < e1; e++) {
            int s = g_csr_src[e];
            acc = fmaf(g_dinv[s] * dm, g_h1[(size_t)s * DIM + t], acc);
        }
        sagg[t * R2 + i] = acc;
    }
    __syncthreads();

    float o[R2];
    {
        const float bb = b2[t];
#pragma unroll
        for (int i = 0; i < R2; i++) o[i] = bb;
    }
#pragma unroll 4
    for (int k = 0; k < DIM; k++) {
        const float w = W2[k * DIM + t];
        const float4* A4 = reinterpret_cast<const float4*>(sagg + k * R2);
        float4 g0 = A4[0], g1 = A4[1], g2 = A4[2], g3 = A4[3];
        o[0]  = fmaf(g0.x, w, o[0]);  o[1]  = fmaf(g0.y, w, o[1]);
        o[2]  = fmaf(g0.z, w, o[2]);  o[3]  = fmaf(g0.w, w, o[3]);
        o[4]  = fmaf(g1.x, w, o[4]);  o[5]  = fmaf(g1.y, w, o[5]);
        o[6]  = fmaf(g1.z, w, o[6]);  o[7]  = fmaf(g1.w, w, o[7]);
        o[8]  = fmaf(g2.x, w, o[8]);  o[9]  = fmaf(g2.y, w, o[9]);
        o[10] = fmaf(g2.z, w, o[10]); o[11] = fmaf(g2.w, w, o[11]);
        o[12] = fmaf(g3.x, w, o[12]); o[13] = fmaf(g3.y, w, o[13]);
        o[14] = fmaf(g3.z, w, o[14]); o[15] = fmaf(g3.w, w, o[15]);
    }
    __syncthreads();
#pragma unroll
    for (int i = 0; i < R2; i++) sagg[i * DIM + t] = o[i];
    __syncthreads();

    const int wi   = t >> 5;
    const int lane = t & 31;
#pragma unroll
    for (int rr = 0; rr < 2; rr++) {
        const int i = wi + rr * 8;
        float v[8];
        float mx = -INFINITY;
#pragma unroll
        for (int j = 0; j < 8; j++) {
            v[j] = sagg[i * DIM + lane + j * 32];
            mx = fmaxf(mx, v[j]);
        }
#pragma unroll
        for (int off = 16; off > 0; off >>= 1)
            mx = fmaxf(mx, __shfl_xor_sync(0xFFFFFFFFu, mx, off));
        float s = 0.f;
#pragma unroll
        for (int j = 0; j < 8; j++) s += expf(v[j] - mx);
#pragma unroll
        for (int off = 16; off > 0; off >>= 1)
            s += __shfl_xor_sync(0xFFFFFFFFu, s, off);
        const float lse = mx + logf(s);
        float* orow = out + (size_t)(r0 + i) * DIM;
#pragma unroll
        for (int j = 0; j < 8; j++) orow[lane + j * 32] = v[j] - lse;
    }
}

// ---------------- launch ----------------
extern "C" void kernel_launch(void* const* d_in, const int* in_sizes, int n_in,
                              void* d_out, int out_size) {
    const int*   x    = (const int*)d_in[0];
    const int*   esrc = (const int*)d_in[1];
    const int*   edst = ((const int*)d_in[1]) + N_EDGES;
    const int*   mask = (const int*)d_in[2];
    const float* emb  = (const float*)d_in[3];
    const float* W1   = (const float*)d_in[4];
    const float* b1   = (const float*)d_in[5];
    const float* W2   = (const float*)d_in[6];
    const float* b2   = (const float*)d_in[7];
    float*       out  = (float*)d_out;

    const int TB = 256;
    k_init_deg<<<(N_NODES + TB - 1) / TB, TB>>>();
    k_hist<<<(N_EDGES + TB - 1) / TB, TB>>>(edst);
    k_blocksum<<<NBLK, SCAN_B>>>();
    k_scanblocks<<<1, 128>>>();
    k_scanfinal<<<NBLK, SCAN_B>>>();
    k_fill<<<(N_EDGES + TB - 1) / TB, TB>>>(esrc, edst);
    k_ew1<<<VOCAB, DIM>>>(emb, W1);
    k_layer1<<<(N_NODES + 7) / 8, 256>>>(x, b1);
    k_layer2<<<N_MASK / R2, 256>>>(mask, W2, b2, out);
}

// round 4
// speedup vs baseline: 2.0237x; 1.1092x over previous
#include <cuda_runtime.h>
#include <math.h>

#define N_NODES 100000
#define N_EDGES 800000
#define VOCAB   256
#define DIM     256
#define N_MASK  10000
#define R2      16
#define SCAN_B  1024
#define NBLK    ((N_NODES + SCAN_B - 1) / SCAN_B)   // 98

// ---------------- scratch (device globals; no runtime allocation) ----------
__device__ int   g_deg[N_NODES];
__device__ float g_dinv[N_NODES];
__device__ int   g_rowstart[N_NODES + 1];
__device__ int   g_cursor[N_NODES];
__device__ int   g_csr_src[N_EDGES];
__device__ int   g_blocksum[NBLK];
__device__ int   g_blockoff[NBLK];
__device__ unsigned char g_need[N_NODES];
__device__ float g_EW1[VOCAB * DIM];
__device__ float g_h1[(size_t)N_NODES * DIM];

// ---------------- helpers ----------------
__device__ __forceinline__ float4 fma4(float w, float4 a, float4 acc) {
    acc.x = fmaf(w, a.x, acc.x);
    acc.y = fmaf(w, a.y, acc.y);
    acc.z = fmaf(w, a.z, acc.z);
    acc.w = fmaf(w, a.w, acc.w);
    return acc;
}

__device__ __forceinline__ int warp_incl_scan(int v, int lane) {
#pragma unroll
    for (int off = 1; off < 32; off <<= 1) {
        int n = __shfl_up_sync(0xFFFFFFFFu, v, off);
        if (lane >= off) v += n;
    }
    return v;
}

// ---------------- CSR construction ----------------
__global__ void k_init_deg() {
    int i = blockIdx.x * blockDim.x + threadIdx.x;
    if (i < N_NODES) { g_deg[i] = 1; g_need[i] = 0; }  // self loop; clear need
}

__global__ void k_hist(const int* __restrict__ dst) {
    int i = blockIdx.x * blockDim.x + threadIdx.x;
    if (i < N_EDGES) atomicAdd(&g_deg[dst[i]], 1);
}

// stage 1: per-block sums of (deg-1)
__global__ void __launch_bounds__(SCAN_B) k_blocksum() {
    __shared__ int wsum[32];
    const int t    = threadIdx.x;
    const int lane = t & 31;
    const int wid  = t >> 5;
    const int i    = blockIdx.x * SCAN_B + t;
    int v = (i < N_NODES) ? g_deg[i] - 1 : 0;
#pragma unroll
    for (int off = 16; off > 0; off >>= 1) v += __shfl_xor_sync(0xFFFFFFFFu, v, off);
    if (lane == 0) wsum[wid] = v;
    __syncthreads();
    if (wid == 0) {
        int s = wsum[lane];
#pragma unroll
        for (int off = 16; off > 0; off >>= 1) s += __shfl_xor_sync(0xFFFFFFFFu, s, off);
        if (lane == 0) g_blocksum[blockIdx.x] = s;
    }
}

// stage 2: exclusive scan of the 98 block sums
__global__ void k_scanblocks() {
    __shared__ int ws[4];
    const int t    = threadIdx.x;     // 128 threads
    const int lane = t & 31;
    const int wid  = t >> 5;
    int v = (t < NBLK) ? g_blocksum[t] : 0;
    int incl = warp_incl_scan(v, lane);
    if (lane == 31) ws[wid] = incl;
    __syncthreads();
    if (t == 0) {
        int run = 0;
#pragma unroll
        for (int w = 0; w < 4; w++) { int tmp = ws[w]; ws[w] = run; run += tmp; }
    }
    __syncthreads();
    if (t < NBLK) g_blockoff[t] = incl - v + ws[wid];
}

// stage 3: per-block exclusive scan + block offset; fold dinv
__global__ void __launch_bounds__(SCAN_B) k_scanfinal() {
    __shared__ int wsum[32];
    const int t    = threadIdx.x;
    const int lane = t & 31;
    const int wid  = t >> 5;
    const int i    = blockIdx.x * SCAN_B + t;
    const int deg  = (i < N_NODES) ? g_deg[i] : 1;
    const int v    = deg - 1;
    int incl = warp_incl_scan(v, lane);
    if (lane == 31) wsum[wid] = incl;
    __syncthreads();
    if (wid == 0) wsum[lane] = warp_incl_scan(wsum[lane], lane);
    __syncthreads();
    int excl = incl - v + (wid ? wsum[wid - 1] : 0) + g_blockoff[blockIdx.x];
    if (i < N_NODES) {
        g_rowstart[i] = excl;
        g_cursor[i]   = excl;
        g_dinv[i]     = rsqrtf((float)deg);
        if (i == N_NODES - 1) g_rowstart[N_NODES] = excl + v;
    }
}

__global__ void k_fill(const int* __restrict__ src, const int* __restrict__ dst) {
    int i = blockIdx.x * blockDim.x + threadIdx.x;
    if (i < N_EDGES) {
        int d = dst[i];
        int p = atomicAdd(&g_cursor[d], 1);
        g_csr_src[p] = src[i];
    }
}

// ---------------- mark nodes whose h1 is actually consumed by layer 2 ------
__global__ void k_mark(const int* __restrict__ mask) {
    const int w = blockIdx.x * (blockDim.x >> 5) + (threadIdx.x >> 5);
    if (w >= N_MASK) return;
    const int lane = threadIdx.x & 31;
    const int m = mask[w];
    if (lane == 0) g_need[m] = 1;
    const int e0 = g_rowstart[m];
    const int e1 = g_rowstart[m + 1];
    for (int e = e0 + lane; e < e1; e += 32) g_need[g_csr_src[e]] = 1;
}

// ---------------- EW1 = emb @ W1 (256x256x256, trivial) ----------------
__global__ void k_ew1(const float* __restrict__ emb, const float* __restrict__ W1) {
    __shared__ float se[DIM];
    const int v = blockIdx.x;
    const int c = threadIdx.x;
    se[c] = emb[v * DIM + c];
    __syncthreads();
    float acc = 0.f;
#pragma unroll 8
    for (int k = 0; k < DIM; k++) acc = fmaf(se[k], W1[k * DIM + c], acc);
    g_EW1[v * DIM + c] = acc;
}

// ---------------- layer 1: h1 = relu(aggregate(EW1[x]) + b1), warp/node ----
__global__ void k_layer1(const int* __restrict__ x, const float* __restrict__ b1) {
    const int warp = blockIdx.x * (blockDim.x >> 5) + (threadIdx.x >> 5);
    if (warp >= N_NODES) return;
    const int n = warp;
    if (!g_need[n]) return;   // h1[n] never read by layer 2
    const int lane = threadIdx.x & 31;

    const float4* EW = reinterpret_cast<const float4*>(g_EW1);
    const float dn = g_dinv[n];

    int   v = x[n];
    float w = dn * dn;
    float4 q0 = EW[v * 64 + lane];
    float4 q1 = EW[v * 64 + 32 + lane];
    float4 a0 = make_float4(w * q0.x, w * q0.y, w * q0.z, w * q0.w);
    float4 a1 = make_float4(w * q1.x, w * q1.y, w * q1.z, w * q1.w);

    const int e0 = g_rowstart[n];
    const int e1 = g_rowstart[n + 1];
    for (int e = e0; e < e1; e++) {
        int s    = g_csr_src[e];
        float ws = g_dinv[s] * dn;
        int  b   = x[s] * 64;
        float4 p0 = EW[b + lane];
        float4 p1 = EW[b + 32 + lane];
        a0 = fma4(ws, p0, a0);
        a1 = fma4(ws, p1, a1);
    }

    const float4* B = reinterpret_cast<const float4*>(b1);
    float4 bb0 = B[lane], bb1 = B[32 + lane];
    a0.x = fmaxf(a0.x + bb0.x, 0.f); a0.y = fmaxf(a0.y + bb0.y, 0.f);
    a0.z = fmaxf(a0.z + bb0.z, 0.f); a0.w = fmaxf(a0.w + bb0.w, 0.f);
    a1.x = fmaxf(a1.x + bb1.x, 0.f); a1.y = fmaxf(a1.y + bb1.y, 0.f);
    a1.z = fmaxf(a1.z + bb1.z, 0.f); a1.w = fmaxf(a1.w + bb1.w, 0.f);

    float4* H = reinterpret_cast<float4*>(g_h1);
    H[(size_t)n * 64 + lane]      = a0;
    H[(size_t)n * 64 + 32 + lane] = a1;
}

// ---------------- layer 2: agg -> GEMM(R2x256x256) -> log_softmax ----------
__global__ void __launch_bounds__(256) k_layer2(const int* __restrict__ mask,
                                                const float* __restrict__ W2,
                                                const float* __restrict__ b2,
                                                float* __restrict__ out) {
    __shared__ float sagg[DIM * R2];
    const int t  = threadIdx.x;
    const int r0 = blockIdx.x * R2;

    for (int i = 0; i < R2; i++) {
        const int m  = mask[r0 + i];
        const float dm = g_dinv[m];
        float acc = dm * dm * g_h1[(size_t)m * DIM + t];
        const int e0 = g_rowstart[m];
        const int e1 = g_rowstart[m + 1];
        for (int e = e0; e < e1; e++) {
            int s = g_csr_src[e];
            acc = fmaf(g_dinv[s] * dm, g_h1[(size_t)s * DIM + t], acc);
        }
        sagg[t * R2 + i] = acc;
    }
    __syncthreads();

    float o[R2];
    {
        const float bb = b2[t];
#pragma unroll
        for (int i = 0; i < R2; i++) o[i] = bb;
    }
#pragma unroll 4
    for (int k = 0; k < DIM; k++) {
        const float w = W2[k * DIM + t];
        const float4* A4 = reinterpret_cast<const float4*>(sagg + k * R2);
        float4 g0 = A4[0], g1 = A4[1], g2 = A4[2], g3 = A4[3];
        o[0]  = fmaf(g0.x, w, o[0]);  o[1]  = fmaf(g0.y, w, o[1]);
        o[2]  = fmaf(g0.z, w, o[2]);  o[3]  = fmaf(g0.w, w, o[3]);
        o[4]  = fmaf(g1.x, w, o[4]);  o[5]  = fmaf(g1.y, w, o[5]);
        o[6]  = fmaf(g1.z, w, o[6]);  o[7]  = fmaf(g1.w, w, o[7]);
        o[8]  = fmaf(g2.x, w, o[8]);  o[9]  = fmaf(g2.y, w, o[9]);
        o[10] = fmaf(g2.z, w, o[10]); o[11] = fmaf(g2.w, w, o[11]);
        o[12] = fmaf(g3.x, w, o[12]); o[13] = fmaf(g3.y, w, o[13]);
        o[14] = fmaf(g3.z, w, o[14]); o[15] = fmaf(g3.w, w, o[15]);
    }
    __syncthreads();
#pragma unroll
    for (int i = 0; i < R2; i++) sagg[i * DIM + t] = o[i];
    __syncthreads();

    const int wi   = t >> 5;
    const int lane = t & 31;
#pragma unroll
    for (int rr = 0; rr < 2; rr++) {
        const int i = wi + rr * 8;
        float v[8];
        float mx = -INFINITY;
#pragma unroll
        for (int j = 0; j < 8; j++) {
            v[j] = sagg[i * DIM + lane + j * 32];
            mx = fmaxf(mx, v[j]);
        }
#pragma unroll
        for (int off = 16; off > 0; off >>= 1)
            mx = fmaxf(mx, __shfl_xor_sync(0xFFFFFFFFu, mx, off));
        float s = 0.f;
#pragma unroll
        for (int j = 0; j < 8; j++) s += expf(v[j] - mx);
#pragma unroll
        for (int off = 16; off > 0; off >>= 1)
            s += __shfl_xor_sync(0xFFFFFFFFu, s, off);
        const float lse = mx + logf(s);
        float* orow = out + (size_t)(r0 + i) * DIM;
#pragma unroll
        for (int j = 0; j < 8; j++) orow[lane + j * 32] = v[j] - lse;
    }
}

// ---------------- launch ----------------
extern "C" void kernel_launch(void* const* d_in, const int* in_sizes, int n_in,
                              void* d_out, int out_size) {
    const int*   x    = (const int*)d_in[0];
    const int*   esrc = (const int*)d_in[1];
    const int*   edst = ((const int*)d_in[1]) + N_EDGES;
    const int*   mask = (const int*)d_in[2];
    const float* emb  = (const float*)d_in[3];
    const float* W1   = (const float*)d_in[4];
    const float* b1   = (const float*)d_in[5];
    const float* W2   = (const float*)d_in[6];
    const float* b2   = (const float*)d_in[7];
    float*       out  = (float*)d_out;

    const int TB = 256;
    k_init_deg<<<(N_NODES + TB - 1) / TB, TB>>>();
    k_hist<<<(N_EDGES + TB - 1) / TB, TB>>>(edst);
    k_blocksum<<<NBLK, SCAN_B>>>();
    k_scanblocks<<<1, 128>>>();
    k_scanfinal<<<NBLK, SCAN_B>>>();
    k_fill<<<(N_EDGES + TB - 1) / TB, TB>>>(esrc, edst);
    k_mark<<<(N_MASK + 7) / 8, 256>>>(mask);
    k_ew1<<<VOCAB, DIM>>>(emb, W1);
    k_layer1<<<(N_NODES + 7) / 8, 256>>>(x, b1);
    k_layer2<<<N_MASK / R2, 256>>>(mask, W2, b2, out);
}